// round 16
// baseline (speedup 1.0000x reference)
#include <cuda_runtime.h>
#include <cuda_bf16.h>
#include <stdint.h>
#include <math.h>

#define NTOK 16384
#define Dm   1024
#define Hm   4096
#define Em   8
#define LSm  1824
#define MTILE 128
#define NTILE 64
#define MAXROWS 33792        // 264 * 128
#define NPASS 4
#define PTILES 66
#define PROWS (PTILES * 128) // 8448
#define BK 16                // bf16 K per chunk (32B data/row)
#define ROWB 48              // 32B data + 16B pad
#define A_PLANE (128 * ROWB)     // 6144
#define B_PLANE (64 * ROWB)      // 3072
#define SLOT_B  (2 * A_PLANE + 2 * B_PLANE)   // 18432; 2 slots = 36864 static

// ------- device scratch: ONE float-typed symbol, 545 MB (R1-proven) -------
__device__ int   g_cnt[Em];
__device__ int   g_off[Em + 1];
__device__ int   g_cursor[Em];
__device__ int   g_top_e[NTOK * 2];
__device__ float g_top_g[NTOK * 2];
__device__ int   g_row_tok[MAXROWS];
__device__ float g_row_gate[MAXROWS];

__device__ __align__(16) float g_scratch[136314880];   // 545,259,520 bytes

// bf16 sub-regions (device-code use ONLY; never passed from host)
#define SCRB ((__nv_bfloat16*)g_scratch)
#define g_xg_hi  (SCRB + 0UL)           // 33792*1024
#define g_xg_lo  (SCRB + 34603008UL)
#define g_h_hi   (SCRB + 69206016UL)    // 8448*4096 (per-pass)
#define g_h_lo   (SCRB + 103809024UL)
#define g_wfc_hi (SCRB + 138412032UL)   // 8*4096*1024 [e][n][k]
#define g_wfc_lo (SCRB + 171966464UL)
#define g_wpj_hi (SCRB + 205520896UL)   // 8*1024*4096 [e][n][k]
#define g_wpj_lo (SCRB + 239075328UL)

#define MMA16816(d, a, b) \
    asm volatile("mma.sync.aligned.m16n8k16.row.col.f32.bf16.bf16.f32 " \
        "{%0,%1,%2,%3}, {%4,%5,%6,%7}, {%8,%9}, {%0,%1,%2,%3};" \
        : "+f"((d)[0]), "+f"((d)[1]), "+f"((d)[2]), "+f"((d)[3]) \
        : "r"((a)[0]), "r"((a)[1]), "r"((a)[2]), "r"((a)[3]), \
          "r"((b)[0]), "r"((b)[1]))
#define LDMX4(r, addr) \
    asm volatile("ldmatrix.sync.aligned.m8n8.x4.shared.b16 {%0,%1,%2,%3}, [%4];" \
        : "=r"((r)[0]), "=r"((r)[1]), "=r"((r)[2]), "=r"((r)[3]) : "r"(addr))
#define LDMX2(r, addr) \
    asm volatile("ldmatrix.sync.aligned.m8n8.x2.shared.b16 {%0,%1}, [%2];" \
        : "=r"((r)[0]), "=r"((r)[1]) : "r"(addr))

__device__ __forceinline__ void split2(float a, float b,
                                       uint32_t& hi, uint32_t& lo) {
    __nv_bfloat162 H = __float22bfloat162_rn(make_float2(a, b));
    uint32_t hbits = *(uint32_t*)&H;
    float ha_f = __uint_as_float(hbits << 16);
    float hb_f = __uint_as_float(hbits & 0xFFFF0000u);
    __nv_bfloat162 L = __float22bfloat162_rn(make_float2(a - ha_f, b - hb_f));
    hi = hbits;
    lo = *(uint32_t*)&L;
}

// ---------------------------------------------------------------------------
__global__ void init_kernel(float* __restrict__ out) {
    if (blockIdx.x == 0 && threadIdx.x < Em) g_cnt[threadIdx.x] = 0;
    const int gtid = blockIdx.x * blockDim.x + threadIdx.x;
    for (int i = gtid; i < MAXROWS; i += gridDim.x * blockDim.x) g_row_tok[i] = -1;
    float4 z = make_float4(0.f, 0.f, 0.f, 0.f);
    float4* o4 = (float4*)out;
    const int n4 = NTOK * Dm / 4;
    for (int i = gtid; i < n4; i += gridDim.x * blockDim.x) o4[i] = z;
}

// ---------------------------------------------------------------------------
__global__ void router_kernel(const float* __restrict__ x,
                              const int*   __restrict__ city_p,
                              const float* __restrict__ dt,
                              const float* __restrict__ dd,
                              const float* __restrict__ drg,
                              const float* __restrict__ de,
                              const float* __restrict__ cemb,
                              const float* __restrict__ Wr,
                              const float* __restrict__ br,
                              float* __restrict__ gate1) {
    const int warp = threadIdx.x >> 5;
    const int lane = threadIdx.x & 31;
    const int t = blockIdx.x * (blockDim.x >> 5) + warp;
    if (t >= NTOK) return;
    const int city = city_p[0];

    float acc[8];
#pragma unroll
    for (int e = 0; e < 8; e++) acc[e] = 0.f;

    for (int l = lane; l < LSm; l += 32) {
        float f;
        if      (l < 1024) f = x  [(size_t)t * 1024 + l];
        else if (l < 1056) f = cemb[city * 32 + (l - 1024)];
        else if (l < 1312) f = dt [(size_t)t * 256 + (l - 1056)];
        else if (l < 1568) f = dd [(size_t)t * 256 + (l - 1312)];
        else if (l < 1696) f = drg[(size_t)t * 128 + (l - 1568)];
        else               f = de [(size_t)t * 128 + (l - 1696)];
        const float4* w4 = (const float4*)(Wr + (size_t)l * 8);
        float4 w0 = w4[0], w1 = w4[1];
        acc[0] = fmaf(f, w0.x, acc[0]); acc[1] = fmaf(f, w0.y, acc[1]);
        acc[2] = fmaf(f, w0.z, acc[2]); acc[3] = fmaf(f, w0.w, acc[3]);
        acc[4] = fmaf(f, w1.x, acc[4]); acc[5] = fmaf(f, w1.y, acc[5]);
        acc[6] = fmaf(f, w1.z, acc[6]); acc[7] = fmaf(f, w1.w, acc[7]);
    }
#pragma unroll
    for (int e = 0; e < 8; e++)
#pragma unroll
        for (int o = 16; o > 0; o >>= 1)
            acc[e] += __shfl_xor_sync(0xffffffffu, acc[e], o);

    if (lane == 0) {
        float lg[8];
#pragma unroll
        for (int e = 0; e < 8; e++) lg[e] = acc[e] + br[e];
        float mx = lg[0];
#pragma unroll
        for (int e = 1; e < 8; e++) mx = fmaxf(mx, lg[e]);
        float ex[8], s = 0.f;
#pragma unroll
        for (int e = 0; e < 8; e++) { ex[e] = expf(lg[e] - mx); s += ex[e]; }
        const float inv = 1.f / s;
#pragma unroll
        for (int e = 0; e < 8; e++) gate1[(size_t)t * 8 + e] = ex[e] * inv;
        int i0 = 0; float v0 = lg[0];
#pragma unroll
        for (int e = 1; e < 8; e++) if (lg[e] > v0) { v0 = lg[e]; i0 = e; }
        int i1 = -1; float v1 = -1e30f;
#pragma unroll
        for (int e = 0; e < 8; e++)
            if (e != i0 && lg[e] > v1) { v1 = lg[e]; i1 = e; }
        const float e1 = expf(v1 - v0);
        const float g0 = 1.f / (1.f + e1);
        const float g1 = e1 / (1.f + e1);
        g_top_e[t * 2 + 0] = i0; g_top_g[t * 2 + 0] = g0;
        g_top_e[t * 2 + 1] = i1; g_top_g[t * 2 + 1] = g1;
        atomicAdd(&g_cnt[i0], 1);
        atomicAdd(&g_cnt[i1], 1);
    }
}

// ---------------------------------------------------------------------------
__global__ void offsets_kernel() {
    int total = 0;
    for (int e = 0; e < Em; e++) {
        g_off[e] = total;
        total += (g_cnt[e] + (MTILE - 1)) & ~(MTILE - 1);
        g_cursor[e] = 0;
    }
    g_off[Em] = total;
}

__global__ void build_kernel() {
    int t = blockIdx.x * blockDim.x + threadIdx.x;
    if (t >= NTOK) return;
#pragma unroll
    for (int j = 0; j < 2; j++) {
        int e = g_top_e[t * 2 + j];
        int pos = atomicAdd(&g_cursor[e], 1);
        int r = g_off[e] + pos;
        g_row_tok[r]  = t;
        g_row_gate[r] = g_top_g[t * 2 + j];
    }
}

// ---------------------------------------------------------------------------
__global__ void gather_kernel(const float* __restrict__ x) {
    const int r = blockIdx.x;
    const int tid = threadIdx.x;
    const int tok = g_row_tok[r];
    float4 v = make_float4(0.f, 0.f, 0.f, 0.f);
    if (tok >= 0) v = ((const float4*)(x + (size_t)tok * Dm))[tid];
    uint32_t h0, l0, h1, l1;
    split2(v.x, v.y, h0, l0);
    split2(v.z, v.w, h1, l1);
    ((uint2*)(g_xg_hi + (size_t)r * Dm))[tid] = make_uint2(h0, h1);
    ((uint2*)(g_xg_lo + (size_t)r * Dm))[tid] = make_uint2(l0, l1);
}

// ---------------------------------------------------------------------------
// convert+transpose weights: W [E][K][N] fp32 -> hi/lo [E][N][K] bf16
// destination selected by flag INSIDE device code (never via host pointer!)
// ---------------------------------------------------------------------------
__global__ void convert_w_kernel(const float* __restrict__ W,
                                 int which, int K, int N) {
    __nv_bfloat16* hi = which ? (__nv_bfloat16*)g_wpj_hi
                              : (__nv_bfloat16*)g_wfc_hi;
    __nv_bfloat16* lo = which ? (__nv_bfloat16*)g_wpj_lo
                              : (__nv_bfloat16*)g_wfc_lo;
    __shared__ float ts[32][33];
    const int e  = blockIdx.z;
    const int n0 = blockIdx.x * 32;
    const int k0 = blockIdx.y * 32;
    const int tx = threadIdx.x, ty = threadIdx.y;
    const float* We = W + (size_t)e * K * N;
#pragma unroll
    for (int i = 0; i < 4; i++)
        ts[ty + 8 * i][tx] = We[(size_t)(k0 + ty + 8 * i) * N + n0 + tx];
    __syncthreads();
    __nv_bfloat16* he = hi + (size_t)e * K * N;
    __nv_bfloat16* le = lo + (size_t)e * K * N;
#pragma unroll
    for (int i = 0; i < 4; i++) {
        float v = ts[tx][ty + 8 * i];
        __nv_bfloat16 h = __float2bfloat16(v);
        __nv_bfloat16 l = __float2bfloat16(v - __bfloat162float(h));
        size_t o = (size_t)(n0 + ty + 8 * i) * K + k0 + tx;
        he[o] = h; le[o] = l;
    }
}

// exact identity: 0.5*(1+tanh(z)) == sigmoid(2z)
__device__ __forceinline__ float gelu_f(float v) {
    float z2 = 1.5957691216057308f * (v + 0.044715f * v * v * v);
    return v / (1.f + __expf(-z2));
}

// ---------------------------------------------------------------------------
// per-chunk MMA via ldmatrix (R12-proven mapping)
// ---------------------------------------------------------------------------
__device__ __forceinline__ void mma_chunk(uint32_t s32, int wm, int wn,
                                          int lane, float (*cacc)[4][4]) {
    const uint32_t a_l = (lane & 15) * ROWB + (lane >> 4) * 16;
    const uint32_t b_l = (lane & 7) * ROWB + ((lane >> 3) & 1) * 16;
    uint32_t bh[4][2], bl[4][2];
#pragma unroll
    for (int nt = 0; nt < 4; nt++) {
        uint32_t ad = s32 + 2 * A_PLANE + (wn * 32 + nt * 8) * ROWB + b_l;
        LDMX2(bh[nt], ad);
        LDMX2(bl[nt], ad + B_PLANE);
    }
#pragma unroll
    for (int mt = 0; mt < 2; mt++) {
        uint32_t ad = s32 + (wm * 32 + mt * 16) * ROWB + a_l;
        uint32_t ah[4], al[4];
        LDMX4(ah, ad);
        LDMX4(al, ad + A_PLANE);
#pragma unroll
        for (int nt = 0; nt < 4; nt++) {
            MMA16816(cacc[mt][nt], ah, bh[nt]);
            MMA16816(cacc[mt][nt], ah, bl[nt]);
            MMA16816(cacc[mt][nt], al, bh[nt]);
        }
    }
}

// STS of prefetched bf16 data (no conversion)
__device__ __forceinline__ void sts_slot(char* slot, int tid,
                                         uint4 aH, uint4 aL,
                                         uint2 bH, uint2 bL) {
    const int ar = tid >> 1, aq = tid & 1;
    *(uint4*)(slot + ar * ROWB + aq * 16) = aH;
    *(uint4*)(slot + A_PLANE + ar * ROWB + aq * 16) = aL;
    const int br_ = tid >> 2, bq = tid & 3;
    *(uint2*)(slot + 2 * A_PLANE + br_ * ROWB + bq * 8) = bH;
    *(uint2*)(slot + 2 * A_PLANE + B_PLANE + br_ * ROWB + bq * 8) = bL;
}

// ---------------------------------------------------------------------------
// fc: h[local,:] = gelu(xg[row] @ Wfc[e]^T + bfc[e]) -> h hi/lo (pass-local)
// ---------------------------------------------------------------------------
__global__ void __launch_bounds__(256, 2)
fc_mma(const float* __restrict__ bfc, int pass) {
    const int mt_i = blockIdx.y;
    const int row0 = pass * PROWS + mt_i * MTILE;
    if (row0 >= g_off[Em]) return;
    int e = 0;
#pragma unroll
    for (int k = 1; k < Em; k++) if (g_off[k] <= row0) e = k;
    const int n0 = blockIdx.x * NTILE;

    __shared__ __align__(16) char smem[2 * SLOT_B];
    const uint32_t s32 = (uint32_t)__cvta_generic_to_shared(smem);
    const int tid = threadIdx.x;
    const int wid = tid >> 5, lane = tid & 31;
    const int wm = wid & 3, wn = wid >> 2;
    const int gr = lane >> 2, tc = lane & 3;

    const __nv_bfloat16* aHg = g_xg_hi + (size_t)row0 * Dm;
    const __nv_bfloat16* aLg = g_xg_lo + (size_t)row0 * Dm;
    const __nv_bfloat16* bHg = g_wfc_hi + ((size_t)e * Hm + n0) * Dm;
    const __nv_bfloat16* bLg = g_wfc_lo + ((size_t)e * Hm + n0) * Dm;

    const int ar = tid >> 1, aq = tid & 1;
    const int br_ = tid >> 2, bq = tid & 3;

    uint4 aH, aL; uint2 bH, bL;
    auto prefetch = [&](int k0) {
        aH = *(const uint4*)(aHg + (size_t)ar * Dm + k0 + aq * 8);
        aL = *(const uint4*)(aLg + (size_t)ar * Dm + k0 + aq * 8);
        bH = *(const uint2*)(bHg + (size_t)br_ * Dm + k0 + bq * 4);
        bL = *(const uint2*)(bLg + (size_t)br_ * Dm + k0 + bq * 4);
    };

    float cacc[2][4][4];
#pragma unroll
    for (int i = 0; i < 2; i++)
#pragma unroll
        for (int j = 0; j < 4; j++)
#pragma unroll
            for (int q = 0; q < 4; q++) cacc[i][j][q] = 0.f;

    const int NC = Dm / BK;
    prefetch(0);
    sts_slot(smem, tid, aH, aL, bH, bL);
    __syncthreads();

    for (int cc = 0; cc < NC; cc++) {
        if (cc + 1 < NC) prefetch((cc + 1) * BK);
        mma_chunk(s32 + (cc & 1) * SLOT_B, wm, wn, lane, cacc);
        if (cc + 1 < NC)
            sts_slot(smem + ((cc + 1) & 1) * SLOT_B, tid, aH, aL, bH, bL);
        __syncthreads();
    }

    const float* bptr = bfc + (size_t)e * Hm + n0 + wn * 32;
    const int lrow0 = mt_i * MTILE + wm * 32;      // pass-local rows
    const int csub = 2 * tc;
#pragma unroll
    for (int mt = 0; mt < 2; mt++) {
        const int r0 = lrow0 + mt * 16 + gr;
        const int r1 = r0 + 8;
#pragma unroll
        for (int nt = 0; nt < 4; nt++) {
            const int coll = wn * 32 + nt * 8 + csub;
            const float b0 = bptr[nt * 8 + csub];
            const float b1 = bptr[nt * 8 + csub + 1];
            float v00 = gelu_f(cacc[mt][nt][0] + b0);
            float v01 = gelu_f(cacc[mt][nt][1] + b1);
            float v10 = gelu_f(cacc[mt][nt][2] + b0);
            float v11 = gelu_f(cacc[mt][nt][3] + b1);
            uint32_t h0, l0, h1, l1;
            split2(v00, v01, h0, l0);
            split2(v10, v11, h1, l1);
            *(uint32_t*)(g_h_hi + (size_t)r0 * Hm + n0 + coll) = h0;
            *(uint32_t*)(g_h_lo + (size_t)r0 * Hm + n0 + coll) = l0;
            *(uint32_t*)(g_h_hi + (size_t)r1 * Hm + n0 + coll) = h1;
            *(uint32_t*)(g_h_lo + (size_t)r1 * Hm + n0 + coll) = l1;
        }
    }
}

// ---------------------------------------------------------------------------
// pj: out[tok(row),:] += gate(row) * (h[local] @ Wpj[e]^T + bproj[e])
// ---------------------------------------------------------------------------
__global__ void __launch_bounds__(256, 2)
pj_mma(const float* __restrict__ bp, float* __restrict__ out, int pass) {
    const int mt_i = blockIdx.y;
    const int row0 = pass * PROWS + mt_i * MTILE;
    if (row0 >= g_off[Em]) return;
    int e = 0;
#pragma unroll
    for (int k = 1; k < Em; k++) if (g_off[k] <= row0) e = k;
    const int n0 = blockIdx.x * NTILE;

    __shared__ __align__(16) char smem[2 * SLOT_B];
    const uint32_t s32 = (uint32_t)__cvta_generic_to_shared(smem);
    const int tid = threadIdx.x;
    const int wid = tid >> 5, lane = tid & 31;
    const int wm = wid & 3, wn = wid >> 2;
    const int gr = lane >> 2, tc = lane & 3;

    const __nv_bfloat16* aHg = g_h_hi + (size_t)(mt_i * MTILE) * Hm;
    const __nv_bfloat16* aLg = g_h_lo + (size_t)(mt_i * MTILE) * Hm;
    const __nv_bfloat16* bHg = g_wpj_hi + ((size_t)e * Dm + n0) * Hm;
    const __nv_bfloat16* bLg = g_wpj_lo + ((size_t)e * Dm + n0) * Hm;

    const int ar = tid >> 1, aq = tid & 1;
    const int br_ = tid >> 2, bq = tid & 3;

    uint4 aH, aL; uint2 bH, bL;
    auto prefetch = [&](int k0) {
        aH = *(const uint4*)(aHg + (size_t)ar * Hm + k0 + aq * 8);
        aL = *(const uint4*)(aLg + (size_t)ar * Hm + k0 + aq * 8);
        bH = *(const uint2*)(bHg + (size_t)br_ * Hm + k0 + bq * 4);
        bL = *(const uint2*)(bLg + (size_t)br_ * Hm + k0 + bq * 4);
    };

    float cacc[2][4][4];
#pragma unroll
    for (int i = 0; i < 2; i++)
#pragma unroll
        for (int j = 0; j < 4; j++)
#pragma unroll
            for (int q = 0; q < 4; q++) cacc[i][j][q] = 0.f;

    const int NC = Hm / BK;
    prefetch(0);
    sts_slot(smem, tid, aH, aL, bH, bL);
    __syncthreads();

    for (int cc = 0; cc < NC; cc++) {
        if (cc + 1 < NC) prefetch((cc + 1) * BK);
        mma_chunk(s32 + (cc & 1) * SLOT_B, wm, wn, lane, cacc);
        if (cc + 1 < NC)
            sts_slot(smem + ((cc + 1) & 1) * SLOT_B, tid, aH, aL, bH, bL);
        __syncthreads();
    }

    const float* bptr = bp + (size_t)e * Dm + n0 + wn * 32;
    const int rbase = row0 + wm * 32;
    const int csub = 2 * tc;
#pragma unroll
    for (int mt = 0; mt < 2; mt++) {
        const int r0 = rbase + mt * 16 + gr;
        const int r1 = r0 + 8;
#pragma unroll
        for (int nt = 0; nt < 4; nt++) {
            const int coll = wn * 32 + nt * 8 + csub;
            const float b0 = bptr[nt * 8 + csub];
            const float b1 = bptr[nt * 8 + csub + 1];
            const int t0 = g_row_tok[r0];
            const int t1 = g_row_tok[r1];
            if (t0 >= 0) {
                const float g = g_row_gate[r0];
                float* op = out + (size_t)t0 * Dm + n0 + coll;
                atomicAdd(op,     g * (cacc[mt][nt][0] + b0));
                atomicAdd(op + 1, g * (cacc[mt][nt][1] + b1));
            }
            if (t1 >= 0) {
                const float g = g_row_gate[r1];
                float* op = out + (size_t)t1 * Dm + n0 + coll;
                atomicAdd(op,     g * (cacc[mt][nt][2] + b0));
                atomicAdd(op + 1, g * (cacc[mt][nt][3] + b1));
            }
        }
    }
}

// ---------------------------------------------------------------------------
extern "C" void kernel_launch(void* const* d_in, const int* in_sizes, int n_in,
                              void* d_out, int out_size) {
    const float* x    = (const float*)d_in[0];
    const int*   city = (const int*)  d_in[1];
    const float* dt   = (const float*)d_in[2];
    const float* dd   = (const float*)d_in[3];
    const float* drg  = (const float*)d_in[4];
    const float* de   = (const float*)d_in[5];
    const float* cemb = (const float*)d_in[6];
    const float* Wr   = (const float*)d_in[7];
    const float* br   = (const float*)d_in[8];
    const float* Wfc  = (const float*)d_in[9];
    const float* bfc  = (const float*)d_in[10];
    const float* Wp   = (const float*)d_in[11];
    const float* bp   = (const float*)d_in[12];

    float* out   = (float*)d_out;
    float* gate1 = out + (size_t)NTOK * Dm;

    init_kernel<<<2048, 256>>>(out);
    router_kernel<<<NTOK / 8, 256>>>(x, city, dt, dd, drg, de, cemb, Wr, br, gate1);
    offsets_kernel<<<1, 1>>>();
    build_kernel<<<NTOK / 256, 256>>>();
    gather_kernel<<<MAXROWS, 256>>>(x);
    convert_w_kernel<<<dim3(Hm / 32, Dm / 32, Em), dim3(32, 8)>>>(Wfc, 0, Dm, Hm);
    convert_w_kernel<<<dim3(Dm / 32, Hm / 32, Em), dim3(32, 8)>>>(Wp, 1, Hm, Dm);

    for (int p = 0; p < NPASS; p++) {
        fc_mma<<<dim3(Hm / NTILE, PTILES), 256>>>(bfc, p);
        pj_mma<<<dim3(Dm / NTILE, PTILES), 256>>>(bp, out, p);
    }
}

// round 17
// speedup vs baseline: 1.0006x; 1.0006x over previous
#include <cuda_runtime.h>
#include <cuda_bf16.h>
#include <stdint.h>
#include <math.h>

#define NTOK 16384
#define Dm   1024
#define Hm   4096
#define Em   8
#define LSm  1824
#define MTILE 128
#define NTILE 64
#define MAXROWS 33792        // 264 * 128
#define NPASS 4
#define PTILES 66
#define PROWS (PTILES * 128) // 8448
#define BK 16                // bf16 K per chunk (32B data/row)
#define ROWB 48              // 32B data + 16B pad
#define A_PLANE (128 * ROWB)     // 6144
#define B_PLANE (64 * ROWB)      // 3072
#define SLOT_B  (2 * A_PLANE + 2 * B_PLANE)   // 18432; 2 slots = 36864 static

// ------- device scratch: ONE float-typed symbol, 545 MB (R1-proven) -------
__device__ int   g_cnt[Em];
__device__ int   g_off[Em + 1];
__device__ int   g_cursor[Em];
__device__ int   g_top_e[NTOK * 2];
__device__ float g_top_g[NTOK * 2];
__device__ int   g_row_tok[MAXROWS];
__device__ float g_row_gate[MAXROWS];

__device__ __align__(16) float g_scratch[136314880];   // 545,259,520 bytes

// bf16 sub-regions (device-code use ONLY; never passed from host)
#define SCRB ((__nv_bfloat16*)g_scratch)
#define g_xg_hi  (SCRB + 0UL)           // 33792*1024
#define g_xg_lo  (SCRB + 34603008UL)
#define g_h_hi   (SCRB + 69206016UL)    // 8448*4096 (per-pass)
#define g_h_lo   (SCRB + 103809024UL)
#define g_wfc_hi (SCRB + 138412032UL)   // 8*4096*1024 [e][n][k]
#define g_wfc_lo (SCRB + 171966464UL)
#define g_wpj_hi (SCRB + 205520896UL)   // 8*1024*4096 [e][n][k]
#define g_wpj_lo (SCRB + 239075328UL)

#define MMA16816(d, a, b) \
    asm volatile("mma.sync.aligned.m16n8k16.row.col.f32.bf16.bf16.f32 " \
        "{%0,%1,%2,%3}, {%4,%5,%6,%7}, {%8,%9}, {%0,%1,%2,%3};" \
        : "+f"((d)[0]), "+f"((d)[1]), "+f"((d)[2]), "+f"((d)[3]) \
        : "r"((a)[0]), "r"((a)[1]), "r"((a)[2]), "r"((a)[3]), \
          "r"((b)[0]), "r"((b)[1]))
#define LDMX4(r, addr) \
    asm volatile("ldmatrix.sync.aligned.m8n8.x4.shared.b16 {%0,%1,%2,%3}, [%4];" \
        : "=r"((r)[0]), "=r"((r)[1]), "=r"((r)[2]), "=r"((r)[3]) : "r"(addr))
#define LDMX2(r, addr) \
    asm volatile("ldmatrix.sync.aligned.m8n8.x2.shared.b16 {%0,%1}, [%2];" \
        : "=r"((r)[0]), "=r"((r)[1]) : "r"(addr))

__device__ __forceinline__ void split2(float a, float b,
                                       uint32_t& hi, uint32_t& lo) {
    __nv_bfloat162 H = __float22bfloat162_rn(make_float2(a, b));
    uint32_t hbits = *(uint32_t*)&H;
    float ha_f = __uint_as_float(hbits << 16);
    float hb_f = __uint_as_float(hbits & 0xFFFF0000u);
    __nv_bfloat162 L = __float22bfloat162_rn(make_float2(a - ha_f, b - hb_f));
    hi = hbits;
    lo = *(uint32_t*)&L;
}

// ---------------------------------------------------------------------------
__global__ void init_kernel(float* __restrict__ out) {
    if (blockIdx.x == 0 && threadIdx.x < Em) g_cnt[threadIdx.x] = 0;
    const int gtid = blockIdx.x * blockDim.x + threadIdx.x;
    for (int i = gtid; i < MAXROWS; i += gridDim.x * blockDim.x) g_row_tok[i] = -1;
    float4 z = make_float4(0.f, 0.f, 0.f, 0.f);
    float4* o4 = (float4*)out;
    const int n4 = NTOK * Dm / 4;
    for (int i = gtid; i < n4; i += gridDim.x * blockDim.x) o4[i] = z;
}

// ---------------------------------------------------------------------------
__global__ void router_kernel(const float* __restrict__ x,
                              const int*   __restrict__ city_p,
                              const float* __restrict__ dt,
                              const float* __restrict__ dd,
                              const float* __restrict__ drg,
                              const float* __restrict__ de,
                              const float* __restrict__ cemb,
                              const float* __restrict__ Wr,
                              const float* __restrict__ br,
                              float* __restrict__ gate1) {
    const int warp = threadIdx.x >> 5;
    const int lane = threadIdx.x & 31;
    const int t = blockIdx.x * (blockDim.x >> 5) + warp;
    if (t >= NTOK) return;
    const int city = city_p[0];

    float acc[8];
#pragma unroll
    for (int e = 0; e < 8; e++) acc[e] = 0.f;

    for (int l = lane; l < LSm; l += 32) {
        float f;
        if      (l < 1024) f = x  [(size_t)t * 1024 + l];
        else if (l < 1056) f = cemb[city * 32 + (l - 1024)];
        else if (l < 1312) f = dt [(size_t)t * 256 + (l - 1056)];
        else if (l < 1568) f = dd [(size_t)t * 256 + (l - 1312)];
        else if (l < 1696) f = drg[(size_t)t * 128 + (l - 1568)];
        else               f = de [(size_t)t * 128 + (l - 1696)];
        const float4* w4 = (const float4*)(Wr + (size_t)l * 8);
        float4 w0 = w4[0], w1 = w4[1];
        acc[0] = fmaf(f, w0.x, acc[0]); acc[1] = fmaf(f, w0.y, acc[1]);
        acc[2] = fmaf(f, w0.z, acc[2]); acc[3] = fmaf(f, w0.w, acc[3]);
        acc[4] = fmaf(f, w1.x, acc[4]); acc[5] = fmaf(f, w1.y, acc[5]);
        acc[6] = fmaf(f, w1.z, acc[6]); acc[7] = fmaf(f, w1.w, acc[7]);
    }
#pragma unroll
    for (int e = 0; e < 8; e++)
#pragma unroll
        for (int o = 16; o > 0; o >>= 1)
            acc[e] += __shfl_xor_sync(0xffffffffu, acc[e], o);

    if (lane == 0) {
        float lg[8];
#pragma unroll
        for (int e = 0; e < 8; e++) lg[e] = acc[e] + br[e];
        float mx = lg[0];
#pragma unroll
        for (int e = 1; e < 8; e++) mx = fmaxf(mx, lg[e]);
        float ex[8], s = 0.f;
#pragma unroll
        for (int e = 0; e < 8; e++) { ex[e] = expf(lg[e] - mx); s += ex[e]; }
        const float inv = 1.f / s;
#pragma unroll
        for (int e = 0; e < 8; e++) gate1[(size_t)t * 8 + e] = ex[e] * inv;
        int i0 = 0; float v0 = lg[0];
#pragma unroll
        for (int e = 1; e < 8; e++) if (lg[e] > v0) { v0 = lg[e]; i0 = e; }
        int i1 = -1; float v1 = -1e30f;
#pragma unroll
        for (int e = 0; e < 8; e++)
            if (e != i0 && lg[e] > v1) { v1 = lg[e]; i1 = e; }
        const float e1 = expf(v1 - v0);
        const float g0 = 1.f / (1.f + e1);
        const float g1 = e1 / (1.f + e1);
        g_top_e[t * 2 + 0] = i0; g_top_g[t * 2 + 0] = g0;
        g_top_e[t * 2 + 1] = i1; g_top_g[t * 2 + 1] = g1;
        atomicAdd(&g_cnt[i0], 1);
        atomicAdd(&g_cnt[i1], 1);
    }
}

// ---------------------------------------------------------------------------
__global__ void offsets_kernel() {
    int total = 0;
    for (int e = 0; e < Em; e++) {
        g_off[e] = total;
        total += (g_cnt[e] + (MTILE - 1)) & ~(MTILE - 1);
        g_cursor[e] = 0;
    }
    g_off[Em] = total;
}

__global__ void build_kernel() {
    int t = blockIdx.x * blockDim.x + threadIdx.x;
    if (t >= NTOK) return;
#pragma unroll
    for (int j = 0; j < 2; j++) {
        int e = g_top_e[t * 2 + j];
        int pos = atomicAdd(&g_cursor[e], 1);
        int r = g_off[e] + pos;
        g_row_tok[r]  = t;
        g_row_gate[r] = g_top_g[t * 2 + j];
    }
}

// ---------------------------------------------------------------------------
__global__ void gather_kernel(const float* __restrict__ x) {
    const int r = blockIdx.x;
    const int tid = threadIdx.x;
    const int tok = g_row_tok[r];
    float4 v = make_float4(0.f, 0.f, 0.f, 0.f);
    if (tok >= 0) v = ((const float4*)(x + (size_t)tok * Dm))[tid];
    uint32_t h0, l0, h1, l1;
    split2(v.x, v.y, h0, l0);
    split2(v.z, v.w, h1, l1);
    ((uint2*)(g_xg_hi + (size_t)r * Dm))[tid] = make_uint2(h0, h1);
    ((uint2*)(g_xg_lo + (size_t)r * Dm))[tid] = make_uint2(l0, l1);
}

// ---------------------------------------------------------------------------
// convert+transpose weights: W [E][K][N] fp32 -> hi/lo [E][N][K] bf16
// destination selected by flag INSIDE device code (never via host pointer!)
// ---------------------------------------------------------------------------
__global__ void convert_w_kernel(const float* __restrict__ W,
                                 int which, int K, int N) {
    __nv_bfloat16* hi = which ? (__nv_bfloat16*)g_wpj_hi
                              : (__nv_bfloat16*)g_wfc_hi;
    __nv_bfloat16* lo = which ? (__nv_bfloat16*)g_wpj_lo
                              : (__nv_bfloat16*)g_wfc_lo;
    __shared__ float ts[32][33];
    const int e  = blockIdx.z;
    const int n0 = blockIdx.x * 32;
    const int k0 = blockIdx.y * 32;
    const int tx = threadIdx.x, ty = threadIdx.y;
    const float* We = W + (size_t)e * K * N;
#pragma unroll
    for (int i = 0; i < 4; i++)
        ts[ty + 8 * i][tx] = We[(size_t)(k0 + ty + 8 * i) * N + n0 + tx];
    __syncthreads();
    __nv_bfloat16* he = hi + (size_t)e * K * N;
    __nv_bfloat16* le = lo + (size_t)e * K * N;
#pragma unroll
    for (int i = 0; i < 4; i++) {
        float v = ts[tx][ty + 8 * i];
        __nv_bfloat16 h = __float2bfloat16(v);
        __nv_bfloat16 l = __float2bfloat16(v - __bfloat162float(h));
        size_t o = (size_t)(n0 + ty + 8 * i) * K + k0 + tx;
        he[o] = h; le[o] = l;
    }
}

// exact identity: 0.5*(1+tanh(z)) == sigmoid(2z)
__device__ __forceinline__ float gelu_f(float v) {
    float z2 = 1.5957691216057308f * (v + 0.044715f * v * v * v);
    return v / (1.f + __expf(-z2));
}

// ---------------------------------------------------------------------------
// per-chunk MMA via ldmatrix (R12-proven mapping)
// ---------------------------------------------------------------------------
__device__ __forceinline__ void mma_chunk(uint32_t s32, int wm, int wn,
                                          int lane, float (*cacc)[4][4]) {
    const uint32_t a_l = (lane & 15) * ROWB + (lane >> 4) * 16;
    const uint32_t b_l = (lane & 7) * ROWB + ((lane >> 3) & 1) * 16;
    uint32_t bh[4][2], bl[4][2];
#pragma unroll
    for (int nt = 0; nt < 4; nt++) {
        uint32_t ad = s32 + 2 * A_PLANE + (wn * 32 + nt * 8) * ROWB + b_l;
        LDMX2(bh[nt], ad);
        LDMX2(bl[nt], ad + B_PLANE);
    }
#pragma unroll
    for (int mt = 0; mt < 2; mt++) {
        uint32_t ad = s32 + (wm * 32 + mt * 16) * ROWB + a_l;
        uint32_t ah[4], al[4];
        LDMX4(ah, ad);
        LDMX4(al, ad + A_PLANE);
#pragma unroll
        for (int nt = 0; nt < 4; nt++) {
            MMA16816(cacc[mt][nt], ah, bh[nt]);
            MMA16816(cacc[mt][nt], ah, bl[nt]);
            MMA16816(cacc[mt][nt], al, bh[nt]);
        }
    }
}

// STS of prefetched bf16 data (no conversion)
__device__ __forceinline__ void sts_slot(char* slot, int tid,
                                         uint4 aH, uint4 aL,
                                         uint2 bH, uint2 bL) {
    const int ar = tid >> 1, aq = tid & 1;
    *(uint4*)(slot + ar * ROWB + aq * 16) = aH;
    *(uint4*)(slot + A_PLANE + ar * ROWB + aq * 16) = aL;
    const int br_ = tid >> 2, bq = tid & 3;
    *(uint2*)(slot + 2 * A_PLANE + br_ * ROWB + bq * 8) = bH;
    *(uint2*)(slot + 2 * A_PLANE + B_PLANE + br_ * ROWB + bq * 8) = bL;
}

// ---------------------------------------------------------------------------
// fc: h[local,:] = gelu(xg[row] @ Wfc[e]^T + bfc[e]) -> h hi/lo (pass-local)
// ---------------------------------------------------------------------------
__global__ void __launch_bounds__(256, 2)
fc_mma(const float* __restrict__ bfc, int pass) {
    const int mt_i = blockIdx.y;
    const int row0 = pass * PROWS + mt_i * MTILE;
    if (row0 >= g_off[Em]) return;
    int e = 0;
#pragma unroll
    for (int k = 1; k < Em; k++) if (g_off[k] <= row0) e = k;
    const int n0 = blockIdx.x * NTILE;

    __shared__ __align__(16) char smem[2 * SLOT_B];
    const uint32_t s32 = (uint32_t)__cvta_generic_to_shared(smem);
    const int tid = threadIdx.x;
    const int wid = tid >> 5, lane = tid & 31;
    const int wm = wid & 3, wn = wid >> 2;
    const int gr = lane >> 2, tc = lane & 3;

    const __nv_bfloat16* aHg = g_xg_hi + (size_t)row0 * Dm;
    const __nv_bfloat16* aLg = g_xg_lo + (size_t)row0 * Dm;
    const __nv_bfloat16* bHg = g_wfc_hi + ((size_t)e * Hm + n0) * Dm;
    const __nv_bfloat16* bLg = g_wfc_lo + ((size_t)e * Hm + n0) * Dm;

    const int ar = tid >> 1, aq = tid & 1;
    const int br_ = tid >> 2, bq = tid & 3;

    uint4 aH, aL; uint2 bH, bL;
    auto prefetch = [&](int k0) {
        aH = *(const uint4*)(aHg + (size_t)ar * Dm + k0 + aq * 8);
        aL = *(const uint4*)(aLg + (size_t)ar * Dm + k0 + aq * 8);
        bH = *(const uint2*)(bHg + (size_t)br_ * Dm + k0 + bq * 4);
        bL = *(const uint2*)(bLg + (size_t)br_ * Dm + k0 + bq * 4);
    };

    float cacc[2][4][4];
#pragma unroll
    for (int i = 0; i < 2; i++)
#pragma unroll
        for (int j = 0; j < 4; j++)
#pragma unroll
            for (int q = 0; q < 4; q++) cacc[i][j][q] = 0.f;

    const int NC = Dm / BK;
    prefetch(0);
    sts_slot(smem, tid, aH, aL, bH, bL);
    __syncthreads();

    for (int cc = 0; cc < NC; cc++) {
        if (cc + 1 < NC) prefetch((cc + 1) * BK);
        mma_chunk(s32 + (cc & 1) * SLOT_B, wm, wn, lane, cacc);
        if (cc + 1 < NC)
            sts_slot(smem + ((cc + 1) & 1) * SLOT_B, tid, aH, aL, bH, bL);
        __syncthreads();
    }

    const float* bptr = bfc + (size_t)e * Hm + n0 + wn * 32;
    const int lrow0 = mt_i * MTILE + wm * 32;      // pass-local rows
    const int csub = 2 * tc;
#pragma unroll
    for (int mt = 0; mt < 2; mt++) {
        const int r0 = lrow0 + mt * 16 + gr;
        const int r1 = r0 + 8;
#pragma unroll
        for (int nt = 0; nt < 4; nt++) {
            const int coll = wn * 32 + nt * 8 + csub;
            const float b0 = bptr[nt * 8 + csub];
            const float b1 = bptr[nt * 8 + csub + 1];
            float v00 = gelu_f(cacc[mt][nt][0] + b0);
            float v01 = gelu_f(cacc[mt][nt][1] + b1);
            float v10 = gelu_f(cacc[mt][nt][2] + b0);
            float v11 = gelu_f(cacc[mt][nt][3] + b1);
            uint32_t h0, l0, h1, l1;
            split2(v00, v01, h0, l0);
            split2(v10, v11, h1, l1);
            *(uint32_t*)(g_h_hi + (size_t)r0 * Hm + n0 + coll) = h0;
            *(uint32_t*)(g_h_lo + (size_t)r0 * Hm + n0 + coll) = l0;
            *(uint32_t*)(g_h_hi + (size_t)r1 * Hm + n0 + coll) = h1;
            *(uint32_t*)(g_h_lo + (size_t)r1 * Hm + n0 + coll) = l1;
        }
    }
}

// ---------------------------------------------------------------------------
// pj: out[tok(row),:] += gate(row) * (h[local] @ Wpj[e]^T + bproj[e])
// ---------------------------------------------------------------------------
__global__ void __launch_bounds__(256, 2)
pj_mma(const float* __restrict__ bp, float* __restrict__ out, int pass) {
    const int mt_i = blockIdx.y;
    const int row0 = pass * PROWS + mt_i * MTILE;
    if (row0 >= g_off[Em]) return;
    int e = 0;
#pragma unroll
    for (int k = 1; k < Em; k++) if (g_off[k] <= row0) e = k;
    const int n0 = blockIdx.x * NTILE;

    __shared__ __align__(16) char smem[2 * SLOT_B];
    const uint32_t s32 = (uint32_t)__cvta_generic_to_shared(smem);
    const int tid = threadIdx.x;
    const int wid = tid >> 5, lane = tid & 31;
    const int wm = wid & 3, wn = wid >> 2;
    const int gr = lane >> 2, tc = lane & 3;

    const __nv_bfloat16* aHg = g_h_hi + (size_t)(mt_i * MTILE) * Hm;
    const __nv_bfloat16* aLg = g_h_lo + (size_t)(mt_i * MTILE) * Hm;
    const __nv_bfloat16* bHg = g_wpj_hi + ((size_t)e * Dm + n0) * Hm;
    const __nv_bfloat16* bLg = g_wpj_lo + ((size_t)e * Dm + n0) * Hm;

    const int ar = tid >> 1, aq = tid & 1;
    const int br_ = tid >> 2, bq = tid & 3;

    uint4 aH, aL; uint2 bH, bL;
    auto prefetch = [&](int k0) {
        aH = *(const uint4*)(aHg + (size_t)ar * Hm + k0 + aq * 8);
        aL = *(const uint4*)(aLg + (size_t)ar * Hm + k0 + aq * 8);
        bH = *(const uint2*)(bHg + (size_t)br_ * Hm + k0 + bq * 4);
        bL = *(const uint2*)(bLg + (size_t)br_ * Hm + k0 + bq * 4);
    };

    float cacc[2][4][4];
#pragma unroll
    for (int i = 0; i < 2; i++)
#pragma unroll
        for (int j = 0; j < 4; j++)
#pragma unroll
            for (int q = 0; q < 4; q++) cacc[i][j][q] = 0.f;

    const int NC = Hm / BK;
    prefetch(0);
    sts_slot(smem, tid, aH, aL, bH, bL);
    __syncthreads();

    for (int cc = 0; cc < NC; cc++) {
        if (cc + 1 < NC) prefetch((cc + 1) * BK);
        mma_chunk(s32 + (cc & 1) * SLOT_B, wm, wn, lane, cacc);
        if (cc + 1 < NC)
            sts_slot(smem + ((cc + 1) & 1) * SLOT_B, tid, aH, aL, bH, bL);
        __syncthreads();
    }

    const float* bptr = bp + (size_t)e * Dm + n0 + wn * 32;
    const int rbase = row0 + wm * 32;
    const int csub = 2 * tc;
#pragma unroll
    for (int mt = 0; mt < 2; mt++) {
        const int r0 = rbase + mt * 16 + gr;
        const int r1 = r0 + 8;
#pragma unroll
        for (int nt = 0; nt < 4; nt++) {
            const int coll = wn * 32 + nt * 8 + csub;
            const float b0 = bptr[nt * 8 + csub];
            const float b1 = bptr[nt * 8 + csub + 1];
            const int t0 = g_row_tok[r0];
            const int t1 = g_row_tok[r1];
            if (t0 >= 0) {
                const float g = g_row_gate[r0];
                float* op = out + (size_t)t0 * Dm + n0 + coll;
                atomicAdd(op,     g * (cacc[mt][nt][0] + b0));
                atomicAdd(op + 1, g * (cacc[mt][nt][1] + b1));
            }
            if (t1 >= 0) {
                const float g = g_row_gate[r1];
                float* op = out + (size_t)t1 * Dm + n0 + coll;
                atomicAdd(op,     g * (cacc[mt][nt][2] + b0));
                atomicAdd(op + 1, g * (cacc[mt][nt][3] + b1));
            }
        }
    }
}

// ---------------------------------------------------------------------------
extern "C" void kernel_launch(void* const* d_in, const int* in_sizes, int n_in,
                              void* d_out, int out_size) {
    const float* x    = (const float*)d_in[0];
    const int*   city = (const int*)  d_in[1];
    const float* dt   = (const float*)d_in[2];
    const float* dd   = (const float*)d_in[3];
    const float* drg  = (const float*)d_in[4];
    const float* de   = (const float*)d_in[5];
    const float* cemb = (const float*)d_in[6];
    const float* Wr   = (const float*)d_in[7];
    const float* br   = (const float*)d_in[8];
    const float* Wfc  = (const float*)d_in[9];
    const float* bfc  = (const float*)d_in[10];
    const float* Wp   = (const float*)d_in[11];
    const float* bp   = (const float*)d_in[12];

    float* out   = (float*)d_out;
    float* gate1 = out + (size_t)NTOK * Dm;

    init_kernel<<<2048, 256>>>(out);
    router_kernel<<<NTOK / 8, 256>>>(x, city, dt, dd, drg, de, cemb, Wr, br, gate1);
    offsets_kernel<<<1, 1>>>();
    build_kernel<<<NTOK / 256, 256>>>();
    gather_kernel<<<MAXROWS, 256>>>(x);
    convert_w_kernel<<<dim3(Hm / 32, Dm / 32, Em), dim3(32, 8)>>>(Wfc, 0, Dm, Hm);
    convert_w_kernel<<<dim3(Dm / 32, Hm / 32, Em), dim3(32, 8)>>>(Wp, 1, Hm, Dm);

    for (int p = 0; p < NPASS; p++) {
        fc_mma<<<dim3(Hm / NTILE, PTILES), 256>>>(bfc, p);
        pj_mma<<<dim3(Dm / NTILE, PTILES), 256>>>(bp, out, p);
    }
}